// round 10
// baseline (speedup 1.0000x reference)
#include <cuda_runtime.h>
#include <cuda.h>
#include <cuda_fp16.h>
#include <cstdint>

// y[n,o] = sum_r sum_m A[r,n,m] * z[r,o,m],  z[r,o,m] = sum_i x[m,i] * W[r,o,i]
// Two kernels with PDL overlap:
//  1) compute_z (HMMA) + output zeroing; triggers dependent launch at start.
//  2) main GEMM: mma.sync fp16, TMA-fed 5-stage k32 pipeline, occ=2.
//     Producer prefetches all A stages before griddepcontrol.wait, then loads B.
// Grid (32, 8): 128-row M-tile x single relation. Partials via atomicAdd.

#define NREL 8
#define NN   4096
#define NF   64

// z scratch, fp16, layout [r][o][m]
__device__ __half g_z[NREL * NF * NN];

// ---------------- PTX helpers ----------------
__device__ __forceinline__ uint32_t smem_u32(const void* p) {
    uint32_t a;
    asm("{ .reg .u64 t; cvta.to.shared.u64 t, %1; cvt.u32.u64 %0, t; }" : "=r"(a) : "l"(p));
    return a;
}

#define GRIDDEP_LAUNCH() asm volatile("griddepcontrol.launch_dependents;" ::: "memory")
#define GRIDDEP_WAIT()   asm volatile("griddepcontrol.wait;" ::: "memory")

#define MBAR_INIT(addr, cnt) \
    asm volatile("mbarrier.init.shared.b64 [%0], %1;" :: "r"(addr), "r"(cnt) : "memory")

#define MBAR_EXPECT_TX(addr, bytes) \
    asm volatile("mbarrier.arrive.expect_tx.shared.b64 _, [%0], %1;" :: "r"(addr), "r"(bytes) : "memory")

#define MBAR_ARRIVE(addr) \
    asm volatile("mbarrier.arrive.shared.b64 _, [%0];" :: "r"(addr) : "memory")

#define MBAR_WAIT(mbar, parity) do {                                              \
    asm volatile("{\n\t.reg .pred P;\n\t"                                         \
        "WL%=:\n\t"                                                               \
        "mbarrier.try_wait.parity.acquire.cta.shared::cta.b64 P, [%0], %1, 0x989680;\n\t" \
        "@P bra.uni WD%=;\n\t"                                                    \
        "bra.uni WL%=;\n\t"                                                       \
        "WD%=:\n\t}"                                                              \
        :: "r"((uint32_t)(mbar)), "r"((uint32_t)(parity)) : "memory");            \
} while (0)

#define MBAR_WAIT_RELAXED(mbar, parity) do {                                      \
    asm volatile("{\n\t.reg .pred P;\n\t"                                         \
        "WL%=:\n\t"                                                               \
        "mbarrier.try_wait.parity.relaxed.cta.shared::cta.b64 P, [%0], %1, 0x989680;\n\t" \
        "@P bra.uni WD%=;\n\t"                                                    \
        "bra.uni WL%=;\n\t"                                                       \
        "WD%=:\n\t}"                                                              \
        :: "r"((uint32_t)(mbar)), "r"((uint32_t)(parity)) : "memory");            \
} while (0)

#define TMA_LD3(smem_addr, map, cx, cy, cz, mbar)                                 \
    asm volatile("cp.async.bulk.tensor.3d.shared::cta.global.tile.mbarrier::complete_tx::bytes " \
        "[%0], [%1, {%2, %3, %4}], [%5];"                                         \
        :: "r"((uint32_t)(smem_addr)), "l"(map), "r"((int)(cx)), "r"((int)(cy)),  \
           "r"((int)(cz)), "r"((uint32_t)(mbar)) : "memory")

__device__ __forceinline__ void mma16816(float* c, const uint32_t* a, const uint32_t* b) {
    asm volatile("mma.sync.aligned.m16n8k16.row.col.f32.f16.f16.f32 "
        "{%0,%1,%2,%3}, {%4,%5,%6,%7}, {%8,%9}, {%0,%1,%2,%3};"
        : "+f"(c[0]), "+f"(c[1]), "+f"(c[2]), "+f"(c[3])
        : "r"(a[0]), "r"(a[1]), "r"(a[2]), "r"(a[3]), "r"(b[0]), "r"(b[1]));
}

__device__ __forceinline__ uint32_t lds_f2_to_h2(uint32_t addr) {
    float x, y;
    asm volatile("ld.shared.v2.f32 {%0,%1}, [%2];" : "=f"(x), "=f"(y) : "r"(addr));
    uint32_t d;
    asm volatile("cvt.rn.f16x2.f32 %0, %1, %2;" : "=r"(d) : "f"(y), "f"(x));
    return d;
}

__device__ __forceinline__ uint32_t lds_u32(uint32_t addr) {
    uint32_t d;
    asm volatile("ld.shared.u32 %0, [%1];" : "=r"(d) : "r"(addr));
    return d;
}

// ---------------- config ----------------
constexpr int NSTAGES      = 5;
constexpr int KSTAGE       = 32;                    // k elems per stage
constexpr int STAGE_A      = 0;                     // 128 rows x 128B fp32 (k32)
constexpr int STAGE_B      = 16384;                 // 64 rows x 64B fp16 (k32)
constexpr int STAGE_BYTES  = 20480;
constexpr int SMEM_REQ     = 1024 + NSTAGES * STAGE_BYTES;  // 103424

// ---------------- kernels ----------------

// Fused: zero d_out + z[r,:,:] = W[r] @ x^T via mma.sync fp16.
// Grid (32, 8), 128 threads. Triggers the dependent (main) launch immediately.
__global__ __launch_bounds__(128) void compute_z_kernel(const float* __restrict__ x,
                                                        const float* __restrict__ w,
                                                        float4* __restrict__ out4) {
    GRIDDEP_LAUNCH();   // let the main kernel start scheduling now

    __shared__ __half wsm[64 * 72];
    __shared__ __half xsm[128 * 72];
    const int tid = threadIdx.x;
    const int r   = blockIdx.y;
    const int m0  = blockIdx.x * 128;

    // zero output: 256 blocks x 256 float4 = 65536 float4 = 262144 floats
    const int bid = blockIdx.y * 32 + blockIdx.x;
    const float4 z4 = make_float4(0.f, 0.f, 0.f, 0.f);
    out4[bid * 256 + tid]       = z4;
    out4[bid * 256 + 128 + tid] = z4;

    // W[r] (64x64 fp32) -> wsm fp16
    const float4* wg = (const float4*)(w + (size_t)r * 4096);
#pragma unroll
    for (int i = tid; i < 1024; i += 128) {
        float4 v = wg[i];
        const int row = i >> 4, col = (i & 15) * 4;
        __half2* d = (__half2*)(wsm + row * 72 + col);
        d[0] = __floats2half2_rn(v.x, v.y);
        d[1] = __floats2half2_rn(v.z, v.w);
    }
    // x[m0:m0+128] (128x64 fp32) -> xsm fp16
    const float4* xg = (const float4*)(x + (size_t)m0 * 64);
#pragma unroll
    for (int i = tid; i < 2048; i += 128) {
        float4 v = xg[i];
        const int row = i >> 4, col = (i & 15) * 4;
        __half2* d = (__half2*)(xsm + row * 72 + col);
        d[0] = __floats2half2_rn(v.x, v.y);
        d[1] = __floats2half2_rn(v.z, v.w);
    }
    __syncthreads();

    const int wid = tid >> 5, lane = tid & 31;
    const int gr = lane >> 2, cp = lane & 3;

    float acc[4][4][4];
#pragma unroll
    for (int ot = 0; ot < 4; ot++)
#pragma unroll
        for (int nt = 0; nt < 4; nt++)
#pragma unroll
            for (int i = 0; i < 4; i++) acc[ot][nt][i] = 0.f;

#pragma unroll
    for (int ks = 0; ks < 4; ks++) {
        const int kb = ks * 16 + cp * 2;  // halves
        uint32_t bf[4][2];
#pragma unroll
        for (int nt = 0; nt < 4; nt++) {
            const __half* bp = xsm + (wid * 32 + nt * 8 + gr) * 72 + kb;
            bf[nt][0] = *(const uint32_t*)bp;
            bf[nt][1] = *(const uint32_t*)(bp + 8);
        }
#pragma unroll
        for (int ot = 0; ot < 4; ot++) {
            const __half* ap = wsm + (ot * 16 + gr) * 72 + kb;
            uint32_t af[4];
            af[0] = *(const uint32_t*)ap;
            af[1] = *(const uint32_t*)(ap + 8 * 72);
            af[2] = *(const uint32_t*)(ap + 8);
            af[3] = *(const uint32_t*)(ap + 8 * 72 + 8);
#pragma unroll
            for (int nt = 0; nt < 4; nt++)
                mma16816(acc[ot][nt], af, bf[nt]);
        }
    }

    // store z fp16: D[o][m]
#pragma unroll
    for (int ot = 0; ot < 4; ot++) {
#pragma unroll
        for (int nt = 0; nt < 4; nt++) {
            const int o = ot * 16 + gr;
            const int m = m0 + wid * 32 + nt * 8 + cp * 2;
            __half2* p0 = (__half2*)(g_z + ((size_t)(r * 64 + o)) * NN + m);
            __half2* p1 = (__half2*)(g_z + ((size_t)(r * 64 + o + 8)) * NN + m);
            *p0 = __floats2half2_rn(acc[ot][nt][0], acc[ot][nt][1]);
            *p1 = __floats2half2_rn(acc[ot][nt][2], acc[ot][nt][3]);
        }
    }
}

// Main GEMM. 160 threads: warps 0-3 consumers (32 rows each), warp 4 TMA producer.
// 2 CTAs per SM (grid 256 on 148 SMs). Producer prefetches A stages before the
// grid-dependency wait; B loads (from g_z) only after the z kernel completed.
__global__ __launch_bounds__(160, 2) void rgcn_main_kernel(
    const __grid_constant__ CUtensorMap tma_a,
    const __grid_constant__ CUtensorMap tma_b,
    float* __restrict__ out) {
    extern __shared__ char smem[];
    const uint32_t sb = smem_u32(smem);
    const int tid  = threadIdx.x;
    const int wid  = tid >> 5;
    const int lane = tid & 31;

    // barriers: full[s] = sb + 16s, empty[s] = sb + 16s + 8
    const uint32_t data0 = (sb + NSTAGES * 16 + 1023) & ~1023u;

    if (tid == 0) {
        for (int s = 0; s < NSTAGES; s++) {
            MBAR_INIT(sb + 16 * s, 1);      // full (tx-based)
            MBAR_INIT(sb + 16 * s + 8, 4);  // empty (4 consumer warps)
        }
    }
    __syncthreads();

    const int NITER = NN / KSTAGE;  // 128

    if (wid == 4) {
        // ---- producer ----
        if (lane == 0) {
            const int mrow = blockIdx.x * 128;
            const int rel  = blockIdx.y;
            // Prefetch A for all stages (independent of z).
            for (int s = 0; s < NSTAGES; s++) {
                MBAR_EXPECT_TX(sb + 16 * s, STAGE_BYTES);
                TMA_LD3(data0 + s * STAGE_BYTES + STAGE_A, &tma_a,
                        s * KSTAGE, mrow, rel, sb + 16 * s);
            }
            // Wait for z kernel grid completion (device-scope flush), then B.
            GRIDDEP_WAIT();
            for (int s = 0; s < NSTAGES; s++)
                TMA_LD3(data0 + s * STAGE_BYTES + STAGE_B, &tma_b,
                        s * KSTAGE, 0, rel, sb + 16 * s);
            // Steady-state loop.
            int s = 0, p = 0;
            for (int it = NSTAGES; it < NITER; it++) {
                MBAR_WAIT_RELAXED(sb + 16 * s + 8, p);
                MBAR_EXPECT_TX(sb + 16 * s, STAGE_BYTES);
                const uint32_t st = data0 + s * STAGE_BYTES;
                const int k0 = it * KSTAGE;
                TMA_LD3(st + STAGE_A, &tma_a, k0, mrow, rel, sb + 16 * s);
                TMA_LD3(st + STAGE_B, &tma_b, k0, 0,    rel, sb + 16 * s);
                if (++s == NSTAGES) { s = 0; p ^= 1; }
            }
        }
    } else {
        // visibility of z + zeroed out for this thread's later accesses
        GRIDDEP_WAIT();

        // ---- consumers: warp w owns rows [w*32, w*32+32) of the 128-row tile ----
        const int w  = wid;
        const int lr = lane >> 2;
        const int cp = lane & 3;
        const uint32_t swa = (uint32_t)lr << 4;        // SW128 (A, 128B rows)
        const uint32_t swb = (uint32_t)(lr & 6) << 3;  // SW64  (B, 64B rows)

        uint32_t a_off0[2], a_off2[2], b_off0[2], b_off1[2];
#pragma unroll
        for (int ks = 0; ks < 2; ks++) {
            a_off0[ks] = ((uint32_t)(ks * 64 + cp * 8))      ^ swa;
            a_off2[ks] = ((uint32_t)(ks * 64 + cp * 8 + 32)) ^ swa;
            b_off0[ks] = ((uint32_t)(ks * 32 + cp * 4))      ^ swb;
            b_off1[ks] = ((uint32_t)(ks * 32 + cp * 4 + 16)) ^ swb;
        }
        uint32_t rowb[2], ob[8];
#pragma unroll
        for (int mt = 0; mt < 2; mt++) rowb[mt] = (uint32_t)(w * 32 + mt * 16 + lr) * 128;
#pragma unroll
        for (int nt = 0; nt < 8; nt++) ob[nt] = STAGE_B + (uint32_t)(nt * 8 + lr) * 64;

        float acc[2][8][4];
#pragma unroll
        for (int mt = 0; mt < 2; mt++)
#pragma unroll
            for (int nt = 0; nt < 8; nt++)
#pragma unroll
                for (int i = 0; i < 4; i++) acc[mt][nt][i] = 0.f;

        int s = 0, p = 0;
        for (int it = 0; it < NITER; it++) {
            MBAR_WAIT(sb + 16 * s, p);
            const uint32_t st = data0 + s * STAGE_BYTES;
#pragma unroll
            for (int ks = 0; ks < 2; ks++) {
                uint32_t bf[8][2];
#pragma unroll
                for (int nt = 0; nt < 8; nt++) {
                    bf[nt][0] = lds_u32(st + ob[nt] + b_off0[ks]);
                    bf[nt][1] = lds_u32(st + ob[nt] + b_off1[ks]);
                }
#pragma unroll
                for (int mt = 0; mt < 2; mt++) {
                    const uint32_t rb = st + rowb[mt];
                    uint32_t af[4];
                    af[0] = lds_f2_to_h2(rb +        a_off0[ks]);
                    af[1] = lds_f2_to_h2(rb + 1024 + a_off0[ks]);
                    af[2] = lds_f2_to_h2(rb +        a_off2[ks]);
                    af[3] = lds_f2_to_h2(rb + 1024 + a_off2[ks]);
#pragma unroll
                    for (int nt = 0; nt < 8; nt++)
                        mma16816(acc[mt][nt], af, bf[nt]);
                }
            }
            if (lane == 0) MBAR_ARRIVE(sb + 16 * s + 8);
            if (++s == NSTAGES) { s = 0; p ^= 1; }
        }

        // epilogue: accumulate partial into (pre-zeroed) out
        const int rbase = blockIdx.x * 128 + w * 32;
#pragma unroll
        for (int mt = 0; mt < 2; mt++) {
#pragma unroll
            for (int nt = 0; nt < 8; nt++) {
                const int row = rbase + mt * 16 + lr;
                const int col = nt * 8 + cp * 2;
                atomicAdd(out + (size_t)row * 64 + col,           acc[mt][nt][0]);
                atomicAdd(out + (size_t)row * 64 + col + 1,       acc[mt][nt][1]);
                atomicAdd(out + (size_t)(row + 8) * 64 + col,     acc[mt][nt][2]);
                atomicAdd(out + (size_t)(row + 8) * 64 + col + 1, acc[mt][nt][3]);
            }
        }
    }
}

// ---------------- host ----------------
typedef CUresult (*PFN_encodeTiled)(CUtensorMap*, CUtensorMapDataType, cuuint32_t, void*,
                                    const cuuint64_t*, const cuuint64_t*, const cuuint32_t*,
                                    const cuuint32_t*, CUtensorMapInterleave, CUtensorMapSwizzle,
                                    CUtensorMapL2promotion, CUtensorMapFloatOOBfill);

extern "C" void kernel_launch(void* const* d_in, const int* in_sizes, int n_in,
                              void* d_out, int out_size) {
    const float* adj = nullptr;
    const float* x = nullptr;
    const float* w = nullptr;
    for (int i = 0; i < n_in; i++) {
        if (in_sizes[i] == NREL * NN * NN)      adj = (const float*)d_in[i];
        else if (in_sizes[i] == NN * NF)        x   = (const float*)d_in[i];
        else if (in_sizes[i] == NREL * NF * NF) w   = (const float*)d_in[i];
    }
    float* out = (float*)d_out;

    void* zptr = nullptr;
    cudaGetSymbolAddress(&zptr, g_z);

    void* fnp = nullptr;
    cudaDriverEntryPointQueryResult qst;
    cudaGetDriverEntryPointByVersion("cuTensorMapEncodeTiled", &fnp, 12000,
                                     cudaEnableDefault, &qst);
    PFN_encodeTiled encode = (PFN_encodeTiled)fnp;

    CUtensorMap tma_a{}, tma_b{};
    {
        cuuint64_t dims[3]    = {NN, NN, NREL};
        cuuint64_t strides[2] = {(cuuint64_t)NN * 4, (cuuint64_t)NN * NN * 4};
        cuuint32_t box[3]     = {32, 128, 1};
        cuuint32_t es[3]      = {1, 1, 1};
        encode(&tma_a, CU_TENSOR_MAP_DATA_TYPE_FLOAT32, 3, (void*)adj, dims, strides, box, es,
               CU_TENSOR_MAP_INTERLEAVE_NONE, CU_TENSOR_MAP_SWIZZLE_128B,
               CU_TENSOR_MAP_L2_PROMOTION_L2_256B, CU_TENSOR_MAP_FLOAT_OOB_FILL_NONE);
    }
    {
        cuuint64_t dims[3]    = {NN, NF, NREL};
        cuuint64_t strides[2] = {(cuuint64_t)NN * 2, (cuuint64_t)NF * NN * 2};
        cuuint32_t box[3]     = {32, 64, 1};
        cuuint32_t es[3]      = {1, 1, 1};
        encode(&tma_b, CU_TENSOR_MAP_DATA_TYPE_FLOAT16, 3, zptr, dims, strides, box, es,
               CU_TENSOR_MAP_INTERLEAVE_NONE, CU_TENSOR_MAP_SWIZZLE_64B,
               CU_TENSOR_MAP_L2_PROMOTION_L2_128B, CU_TENSOR_MAP_FLOAT_OOB_FILL_NONE);
    }

    cudaFuncSetAttribute(rgcn_main_kernel, cudaFuncAttributeMaxDynamicSharedMemorySize, SMEM_REQ);

    compute_z_kernel<<<dim3(32, 8), 128>>>(x, w, (float4*)out);

    // PDL launch of the main kernel; fall back to a plain launch on any error.
    cudaLaunchConfig_t cfg = {};
    cfg.gridDim          = dim3(32, 8);
    cfg.blockDim         = dim3(160);
    cfg.dynamicSmemBytes = SMEM_REQ;
    cfg.stream           = 0;
    cudaLaunchAttribute at[1];
    at[0].id = cudaLaunchAttributeProgrammaticStreamSerialization;
    at[0].val.programmaticStreamSerializationAllowed = 1;
    cfg.attrs    = at;
    cfg.numAttrs = 1;
    cudaError_t e = cudaLaunchKernelEx(&cfg, rgcn_main_kernel, tma_a, tma_b, out);
    if (e != cudaSuccess) {
        rgcn_main_kernel<<<dim3(32, 8), 160, SMEM_REQ>>>(tma_a, tma_b, out);
    }
}